// round 7
// baseline (speedup 1.0000x reference)
#include <cuda_runtime.h>
#include <cuda_bf16.h>
#include <cstdint>

#define DEV_INLINE __device__ __forceinline__

// Problem constants
constexpr int Bb = 2, Sq = 2048, Dd = 2048, Hh = 16, DHd = 128;
constexpr int Mrows = Bb * Sq;              // 4096
constexpr float SM_SCALE = 0.08838834764831845f;  // 1/sqrt(128)

// Scratch (device globals -- no allocation allowed)
__device__ float g_Q[(size_t)Mrows * Dd];
__device__ float g_K[(size_t)Mrows * Dd];
__device__ float g_V[(size_t)Mrows * Dd];
__device__ float g_O[(size_t)Mrows * Dd];

DEV_INLINE uint32_t f2tf(float f) {
    uint32_t r;
    asm("cvt.rna.tf32.f32 %0, %1;" : "=r"(r) : "f"(f));
    return r;
}

DEV_INLINE void mma_tf32(float* c, const uint32_t* a, uint32_t b0, uint32_t b1) {
    asm volatile(
        "mma.sync.aligned.m16n8k8.row.col.f32.tf32.tf32.f32 "
        "{%0,%1,%2,%3},{%4,%5,%6,%7},{%8,%9},{%0,%1,%2,%3};"
        : "+f"(c[0]), "+f"(c[1]), "+f"(c[2]), "+f"(c[3])
        : "r"(a[0]), "r"(a[1]), "r"(a[2]), "r"(a[3]), "r"(b0), "r"(b1));
}

DEV_INLINE uint32_t smem_u32(const void* p) {
    uint32_t a;
    asm("{ .reg .u64 t; cvta.to.shared.u64 t, %1; cvt.u32.u64 %0, t; }"
        : "=r"(a) : "l"(p));
    return a;
}

#define CP_ASYNC16(dst, src) \
    asm volatile("cp.async.cg.shared.global [%0], [%1], 16;" :: "r"(dst), "l"(src))
#define CP_COMMIT() asm volatile("cp.async.commit_group;" ::: "memory")
#define CP_WAIT2() asm volatile("cp.async.wait_group 2;" ::: "memory")

// ---------------------------------------------------------------------------
// GEMM v3: C = A[M,2048] * W[N,2048]^T, CTA tile 128(M) x 256(N), K-slab 32.
// 256 threads, warp grid 2(m) x 4(n), warp tile 64x64 (mi=4, nj=8).
// 3-stage cp.async pipeline (raw fp32 in SMEM, tf32 RNA cvt at fragment load).
// KIND 0: fused QKV (z: 0=Q rope+scale, 1=K rope, 2=V; head-major out)
// KIND 1: output projection (fp32 [M,N])
// ---------------------------------------------------------------------------
constexpr int LDSX = 36;                      // 32 + 4 pad
constexpr int SSF = (128 + 256) * LDSX;       // floats per stage = 13824
constexpr int GEMM_SMEM = 3 * SSF * 4;        // 165888 B

template <int KIND>
__global__ __launch_bounds__(256)
void gemm3(const float* __restrict__ A,
           const float* __restrict__ W0, const float* __restrict__ W1,
           const float* __restrict__ W2,
           float* __restrict__ C0, float* __restrict__ C1,
           float* __restrict__ C2,
           const float* __restrict__ cosT, const float* __restrict__ sinT) {
    constexpr int KDIM = 2048;
    constexpr int NSLAB = KDIM / 32;  // 64
    extern __shared__ float sm3[];
    const uint32_t sb = smem_u32(sm3);

    const int tid = threadIdx.x;
    const int lane = tid & 31, warp = tid >> 5;
    const int wm = warp >> 2, wn = warp & 3;  // 2 x 4 warps
    const int bm = blockIdx.y * 128, bn = blockIdx.x * 256;
    const int mode = (KIND == 0) ? (int)blockIdx.z : 3;
    const float* W = (KIND == 0)
                         ? (blockIdx.z == 0 ? W0 : (blockIdx.z == 1 ? W1 : W2))
                         : W0;
    float* C = (KIND == 0)
                   ? (blockIdx.z == 0 ? C0 : (blockIdx.z == 1 ? C1 : C2))
                   : C0;

    const int arow = tid >> 3, ac4 = tid & 7;
    // Per-thread smem dst offsets within a stage (bytes)
    const uint32_t dA = (uint32_t)(arow * LDSX + ac4 * 4) * 4u;
    const uint32_t dW = (uint32_t)((128 + arow) * LDSX + ac4 * 4) * 4u;
    const float* gA = A + (size_t)(bm + arow) * KDIM + ac4 * 4;
    const float* gW = W + (size_t)(bn + arow) * KDIM + ac4 * 4;

    float acc[4][8][4];
#pragma unroll
    for (int i = 0; i < 4; ++i)
#pragma unroll
        for (int j = 0; j < 8; ++j)
#pragma unroll
            for (int e = 0; e < 4; ++e) acc[i][j][e] = 0.f;

    // ---- pipeline: issue stage s -> buffer s%3, group s ----
    auto issue = [&](int s) {
        const uint32_t sbase = sb + (uint32_t)((s % 3) * SSF) * 4u;
        const int k0 = s * 32;
#pragma unroll
        for (int i = 0; i < 4; ++i)
            CP_ASYNC16(sbase + dA + (uint32_t)(i * 32 * LDSX) * 4u,
                       gA + (size_t)(i * 32) * KDIM + k0);
#pragma unroll
        for (int i = 0; i < 8; ++i)
            CP_ASYNC16(sbase + dW + (uint32_t)(i * 32 * LDSX) * 4u,
                       gW + (size_t)(i * 32) * KDIM + k0);
    };

    issue(0); CP_COMMIT();
    issue(1); CP_COMMIT();

    for (int s = 0; s < NSLAB; ++s) {
        if (s + 2 < NSLAB) issue(s + 2);
        CP_COMMIT();          // commit every iter (possibly empty) to keep count
        CP_WAIT2();           // group s complete
        __syncthreads();

        const float* As = sm3 + (s % 3) * SSF;
        const float* Ws = As + 128 * LDSX;
#pragma unroll
        for (int ks = 0; ks < 4; ++ks) {
            const int cfr = ks * 8 + (lane & 3);
            uint32_t af[4][4];
#pragma unroll
            for (int mi = 0; mi < 4; ++mi) {
                int r = wm * 64 + mi * 16 + (lane >> 2);
                af[mi][0] = f2tf(As[r * LDSX + cfr]);
                af[mi][1] = f2tf(As[(r + 8) * LDSX + cfr]);
                af[mi][2] = f2tf(As[r * LDSX + cfr + 4]);
                af[mi][3] = f2tf(As[(r + 8) * LDSX + cfr + 4]);
            }
#pragma unroll
            for (int nj = 0; nj < 8; ++nj) {
                int n = wn * 64 + nj * 8 + (lane >> 2);
                uint32_t b0 = f2tf(Ws[n * LDSX + cfr]);
                uint32_t b1 = f2tf(Ws[n * LDSX + cfr + 4]);
#pragma unroll
                for (int mi = 0; mi < 4; ++mi)
                    mma_tf32(acc[mi][nj], af[mi], b0, b1);
            }
        }
        __syncthreads();  // stage buffer free for reuse by iter s+1's issue
    }

    // Epilogue
#pragma unroll
    for (int mi = 0; mi < 4; ++mi) {
#pragma unroll
        for (int nj = 0; nj < 8; ++nj) {
            int r0 = bm + wm * 64 + mi * 16 + (lane >> 2);
            int c = bn + wn * 64 + nj * 8 + (lane & 3) * 2;
            float v00 = acc[mi][nj][0], v01 = acc[mi][nj][1];
            float v10 = acc[mi][nj][2], v11 = acc[mi][nj][3];
            if (mode <= 1) {
                int i = (c & 127) >> 1;
                {
                    int s = r0 & (Sq - 1);
                    float cs = cosT[s * 64 + i], sn = sinT[s * 64 + i];
                    float t0 = v00 * cs - v01 * sn;
                    float t1 = v00 * sn + v01 * cs;
                    if (mode == 0) { t0 *= SM_SCALE; t1 *= SM_SCALE; }
                    v00 = t0; v01 = t1;
                }
                {
                    int s = (r0 + 8) & (Sq - 1);
                    float cs = cosT[s * 64 + i], sn = sinT[s * 64 + i];
                    float t0 = v10 * cs - v11 * sn;
                    float t1 = v10 * sn + v11 * cs;
                    if (mode == 0) { t0 *= SM_SCALE; t1 *= SM_SCALE; }
                    v10 = t0; v11 = t1;
                }
            }
            if (mode == 3) {
                float2 lo = {v00, v01}, hi = {v10, v11};
                *(float2*)&C[(size_t)r0 * Dd + c] = lo;
                *(float2*)&C[(size_t)(r0 + 8) * Dd + c] = hi;
            } else {
                int h = c >> 7, d = c & 127;
                int b0i = r0 >> 11, s0 = r0 & (Sq - 1);
                int s1 = (r0 + 8) & (Sq - 1);
                size_t o0 = (((size_t)b0i * Hh + h) * Sq + s0) * DHd + d;
                size_t o1 = (((size_t)b0i * Hh + h) * Sq + s1) * DHd + d;
                float2 lo = {v00, v01}, hi = {v10, v11};
                *(float2*)&C[o0] = lo;
                *(float2*)&C[o1] = hi;
            }
        }
    }
}

// ---------------------------------------------------------------------------
// Flash attention (unchanged, known-good): grid (S/64, B*H), 128 threads.
// ---------------------------------------------------------------------------
__global__ __launch_bounds__(128)
void attn_kernel(const float* __restrict__ Q, const float* __restrict__ K,
                 const float* __restrict__ V, float* __restrict__ O) {
    extern __shared__ float sm[];
    constexpr int LKV = 132;  // 128 + 4 pad
    constexpr int LP = 68;    // 64 + 4 pad
    float* Ks = sm;
    float* Vs = sm + 64 * LKV;
    float* Xs = sm + 2 * 64 * LKV;

    const int tid = threadIdx.x, lane = tid & 31, warp = tid >> 5;
    const int qt = blockIdx.x, bh = blockIdx.y;
    const size_t base = (size_t)bh * Sq * DHd;

    const float* Qg = Q + base + (size_t)qt * 64 * DHd;
    for (int i = tid; i < 64 * 32; i += 128) {
        int r = i >> 5, cc = i & 31;
        float4 v = *(const float4*)&Qg[r * 128 + cc * 4];
        uint4 t = {f2tf(v.x), f2tf(v.y), f2tf(v.z), f2tf(v.w)};
        *(uint4*)&Xs[r * LKV + cc * 4] = t;
    }
    __syncthreads();
    uint32_t qf[16][4];
    {
        const uint32_t* Xu = (const uint32_t*)Xs;
#pragma unroll
        for (int ks = 0; ks < 16; ++ks) {
            int r = warp * 16 + (lane >> 2);
            int c = ks * 8 + (lane & 3);
            qf[ks][0] = Xu[r * LKV + c];
            qf[ks][1] = Xu[(r + 8) * LKV + c];
            qf[ks][2] = Xu[r * LKV + c + 4];
            qf[ks][3] = Xu[(r + 8) * LKV + c + 4];
        }
    }
    __syncthreads();

    float oa[16][4];
#pragma unroll
    for (int j = 0; j < 16; ++j)
#pragma unroll
        for (int e = 0; e < 4; ++e) oa[j][e] = 0.f;
    float mrow[2] = {-1e30f, -1e30f}, lrow[2] = {0.f, 0.f};

    uint32_t* Pu = (uint32_t*)(Xs + warp * (16 * LP));

    for (int kt = 0; kt <= qt; ++kt) {
        __syncthreads();
        const float* Kg = K + base + (size_t)kt * 64 * DHd;
        const float* Vg = V + base + (size_t)kt * 64 * DHd;
        for (int i = tid; i < 64 * 32; i += 128) {
            int r = i >> 5, cc = i & 31;
            float4 v = *(const float4*)&Kg[r * 128 + cc * 4];
            uint4 t = {f2tf(v.x), f2tf(v.y), f2tf(v.z), f2tf(v.w)};
            *(uint4*)&Ks[r * LKV + cc * 4] = t;
            float4 w = *(const float4*)&Vg[r * 128 + cc * 4];
            uint4 u = {f2tf(w.x), f2tf(w.y), f2tf(w.z), f2tf(w.w)};
            *(uint4*)&Vs[r * LKV + cc * 4] = u;
        }
        __syncthreads();

        float sc[8][4];
#pragma unroll
        for (int j = 0; j < 8; ++j)
#pragma unroll
            for (int e = 0; e < 4; ++e) sc[j][e] = 0.f;
        {
            const uint32_t* Ku = (const uint32_t*)Ks;
#pragma unroll
            for (int ks = 0; ks < 16; ++ks) {
#pragma unroll
                for (int j = 0; j < 8; ++j) {
                    int n = j * 8 + (lane >> 2);
                    int c = ks * 8 + (lane & 3);
                    uint32_t b0 = Ku[n * LKV + c];
                    uint32_t b1 = Ku[n * LKV + c + 4];
                    mma_tf32(sc[j], qf[ks], b0, b1);
                }
            }
        }

        if (kt == qt) {
            int rl = warp * 16 + (lane >> 2);
#pragma unroll
            for (int j = 0; j < 8; ++j) {
                int cb = j * 8 + (lane & 3) * 2;
                if (cb > rl) sc[j][0] = -1e30f;
                if (cb + 1 > rl) sc[j][1] = -1e30f;
                if (cb > rl + 8) sc[j][2] = -1e30f;
                if (cb + 1 > rl + 8) sc[j][3] = -1e30f;
            }
        }

        float mx0 = -1e30f, mx1 = -1e30f;
#pragma unroll
        for (int j = 0; j < 8; ++j) {
            mx0 = fmaxf(mx0, fmaxf(sc[j][0], sc[j][1]));
            mx1 = fmaxf(mx1, fmaxf(sc[j][2], sc[j][3]));
        }
        mx0 = fmaxf(mx0, __shfl_xor_sync(0xffffffffu, mx0, 1));
        mx0 = fmaxf(mx0, __shfl_xor_sync(0xffffffffu, mx0, 2));
        mx1 = fmaxf(mx1, __shfl_xor_sync(0xffffffffu, mx1, 1));
        mx1 = fmaxf(mx1, __shfl_xor_sync(0xffffffffu, mx1, 2));
        float nm0 = fmaxf(mrow[0], mx0), nm1 = fmaxf(mrow[1], mx1);
        float f0 = __expf(mrow[0] - nm0), f1 = __expf(mrow[1] - nm1);
        float s0 = 0.f, s1 = 0.f;
#pragma unroll
        for (int j = 0; j < 8; ++j) {
            sc[j][0] = __expf(sc[j][0] - nm0);
            sc[j][1] = __expf(sc[j][1] - nm0);
            sc[j][2] = __expf(sc[j][2] - nm1);
            sc[j][3] = __expf(sc[j][3] - nm1);
            s0 += sc[j][0] + sc[j][1];
            s1 += sc[j][2] + sc[j][3];
        }
        s0 += __shfl_xor_sync(0xffffffffu, s0, 1);
        s0 += __shfl_xor_sync(0xffffffffu, s0, 2);
        s1 += __shfl_xor_sync(0xffffffffu, s1, 1);
        s1 += __shfl_xor_sync(0xffffffffu, s1, 2);
        lrow[0] = lrow[0] * f0 + s0;
        lrow[1] = lrow[1] * f1 + s1;
        mrow[0] = nm0;
        mrow[1] = nm1;
#pragma unroll
        for (int j = 0; j < 16; ++j) {
            oa[j][0] *= f0; oa[j][1] *= f0;
            oa[j][2] *= f1; oa[j][3] *= f1;
        }

        __syncwarp();
        {
            int r = lane >> 2, cb = (lane & 3) * 2;
#pragma unroll
            for (int j = 0; j < 8; ++j) {
                Pu[r * LP + j * 8 + cb] = f2tf(sc[j][0]);
                Pu[r * LP + j * 8 + cb + 1] = f2tf(sc[j][1]);
                Pu[(r + 8) * LP + j * 8 + cb] = f2tf(sc[j][2]);
                Pu[(r + 8) * LP + j * 8 + cb + 1] = f2tf(sc[j][3]);
            }
        }
        __syncwarp();
        {
            const uint32_t* Vu = (const uint32_t*)Vs;
#pragma unroll
            for (int ks = 0; ks < 8; ++ks) {
                uint32_t a[4];
                int r = lane >> 2, c = ks * 8 + (lane & 3);
                a[0] = Pu[r * LP + c];
                a[1] = Pu[(r + 8) * LP + c];
                a[2] = Pu[r * LP + c + 4];
                a[3] = Pu[(r + 8) * LP + c + 4];
                int kv = ks * 8 + (lane & 3);
#pragma unroll
                for (int j = 0; j < 16; ++j) {
                    int dcol = j * 8 + (lane >> 2);
                    uint32_t b0 = Vu[kv * LKV + dcol];
                    uint32_t b1 = Vu[(kv + 4) * LKV + dcol];
                    mma_tf32(oa[j], a, b0, b1);
                }
            }
        }
        __syncwarp();
    }

    float i0 = 1.f / lrow[0], i1 = 1.f / lrow[1];
    int b = bh >> 4, h = bh & 15;
    int r0 = qt * 64 + warp * 16 + (lane >> 2);
    float* Og = O + ((size_t)b * Sq + r0) * Dd + h * DHd;
#pragma unroll
    for (int j = 0; j < 16; ++j) {
        int dcol = j * 8 + (lane & 3) * 2;
        float2 lo = {oa[j][0] * i0, oa[j][1] * i0};
        float2 hi = {oa[j][2] * i1, oa[j][3] * i1};
        *(float2*)&Og[dcol] = lo;
        *(float2*)&Og[(size_t)8 * Dd + dcol] = hi;
    }
}

// ---------------------------------------------------------------------------
extern "C" void kernel_launch(void* const* d_in, const int* in_sizes, int n_in,
                              void* d_out, int out_size) {
    const float* x = (const float*)d_in[0];
    const float* fc = (const float*)d_in[1];
    const float* fs = (const float*)d_in[2];
    // d_in[3] = mask (unused; causality handled analytically)
    const float* wq = (const float*)d_in[4];
    const float* wk = (const float*)d_in[5];
    const float* wv = (const float*)d_in[6];
    const float* wo = (const float*)d_in[7];
    float* out = (float*)d_out;

    float *Qp, *Kp, *Vp, *Op;
    cudaGetSymbolAddress((void**)&Qp, g_Q);
    cudaGetSymbolAddress((void**)&Kp, g_K);
    cudaGetSymbolAddress((void**)&Vp, g_V);
    cudaGetSymbolAddress((void**)&Op, g_O);

    cudaFuncSetAttribute(gemm3<0>, cudaFuncAttributeMaxDynamicSharedMemorySize,
                         GEMM_SMEM);
    cudaFuncSetAttribute(gemm3<1>, cudaFuncAttributeMaxDynamicSharedMemorySize,
                         GEMM_SMEM);

    // Fused QKV projections (z = 0:Q, 1:K, 2:V)
    gemm3<0><<<dim3(Dd / 256, Mrows / 128, 3), 256, GEMM_SMEM>>>(
        x, wq, wk, wv, Qp, Kp, Vp, fc, fs);

    constexpr int ATTN_SMEM = (3 * 64 * 132) * 4;  // 101376 bytes
    cudaFuncSetAttribute(attn_kernel, cudaFuncAttributeMaxDynamicSharedMemorySize,
                         ATTN_SMEM);
    attn_kernel<<<dim3(Sq / 64, Bb * Hh), 128, ATTN_SMEM>>>(Qp, Kp, Vp, Op);

    // Output projection
    gemm3<1><<<dim3(Dd / 256, Mrows / 128, 1), 256, GEMM_SMEM>>>(
        Op, wo, nullptr, nullptr, out, nullptr, nullptr, fc, fs);
}